// round 15
// baseline (speedup 1.0000x reference)
#include <cuda_runtime.h>
#include <cuda_bf16.h>
#include <mma.h>
#include <math.h>
#include <cstdint>

using namespace nvcuda;

#define NB 8
#define NT 512
#define NS 128
#define NC 512
#define RR 19
#define NS1 129
#define NT1 513
#define NT1P 520
#define MROWS (NB*NT*RR)
#define NEGF (-1e20f)

// ---------------- device scratch (allocation-free module globals) -----------
__device__ float g_lm_max[NB*NS1];
__device__ float g_lm_lse[NB*NS1];
__device__ float g_lm_p[(size_t)NB*NS1*NC];
__device__ float g_am_max[NB*NT];
__device__ float g_am_p[(size_t)NB*NT*NC];
__device__ float g_px[(size_t)NB*NS*NT1];
__device__ float g_py[(size_t)NB*NS1*NT];
__device__ float g_alpha[(size_t)NB*NS1*NT1P];
__device__ float g_beta[(size_t)NB*NS1*NT1P];
__device__ float g_total[NB];
__device__ float g_total2[NB];
__device__ float g_pxg[(size_t)NB*NS*NT1];
__device__ float g_pyg[(size_t)NB*NS1*NT];
__device__ int   g_sb[NB*NT];
__device__ __nv_bfloat16 g_A[(size_t)MROWS*NC];
__device__ __nv_bfloat16 g_W[NC*NC];
__device__ float g_pmax[(size_t)MROWS*4];
__device__ float g_psum[(size_t)MROWS*4];
__device__ float g_pxv[MROWS];
__device__ float g_pyv[MROWS];
__device__ float g_pxf[(size_t)NB*NS*NT1];
__device__ float g_pyf[(size_t)NB*NS1*NT];

// ---------------- helpers ----------------
__device__ __forceinline__ float warpmax(float v){
  #pragma unroll
  for(int o=16;o>0;o>>=1) v=fmaxf(v,__shfl_xor_sync(0xffffffffu,v,o));
  return v;
}
__device__ __forceinline__ float warpsum(float v){
  #pragma unroll
  for(int o=16;o>0;o>>=1) v+=__shfl_xor_sync(0xffffffffu,v,o);
  return v;
}
// fast logaddexp via MUFU ex2/lg2 (err ~1e-7 abs)
__device__ __forceinline__ float lae2(float a,float b){
  float mx=fmaxf(a,b), mn=fminf(a,b);
  float d = (mn-mx)*1.4426950408889634f;
  float e; asm("ex2.approx.f32 %0, %1;" : "=f"(e) : "f"(d));
  float l; asm("lg2.approx.f32 %0, %1;" : "=f"(l) : "f"(1.0f+e));
  return mx + l*0.6931471805599453f;
}
__device__ __forceinline__ float tanh_ap(float x){
  float r; asm("tanh.approx.f32 %0, %1;" : "=f"(r) : "f"(x)); return r;
}
__device__ __forceinline__ void cp16(uint32_t dst, const void* src){
  asm volatile("cp.async.cg.shared.global [%0], [%1], 16;" :: "r"(dst), "l"(src));
}

// ---------------- merged row stats (lm rows then am rows) -------------------
__global__ void k_stats(const float* __restrict__ lm, const float* __restrict__ am){
  int row = blockIdx.x*8 + (threadIdx.x>>5);
  int lane = threadIdx.x & 31;
  if(row < NB*NS1){
    const float* L = lm + (size_t)row*NC;
    float v[16]; float mx = -3.4e38f;
    #pragma unroll
    for(int j=0;j<16;j++){ v[j]=L[lane+32*j]; mx=fmaxf(mx,v[j]); }
    mx = warpmax(mx);
    float s = 0.f;
    #pragma unroll
    for(int j=0;j<16;j++){ float e=expf(v[j]-mx); s+=e; g_lm_p[(size_t)row*NC+lane+32*j]=e; }
    s = warpsum(s);
    if(lane==0){ g_lm_max[row]=mx; g_lm_lse[row]=mx+logf(s); }
  } else {
    int r = row - NB*NS1;
    if(r >= NB*NT) return;
    const float* A = am + (size_t)r*NC;
    float v[16]; float mx = -3.4e38f;
    #pragma unroll
    for(int j=0;j<16;j++){ v[j]=A[lane+32*j]; mx=fmaxf(mx,v[j]); }
    mx = warpmax(mx);
    #pragma unroll
    for(int j=0;j<16;j++) g_am_p[(size_t)r*NC + lane+32*j] = expf(v[j]-mx);
    if(lane==0) g_am_max[r]=mx;
  }
}

// ---- normalizers (64x64 tile, 4x4 reg blocking) + fused px/py epilogue -----
__global__ void __launch_bounds__(256) k_norm(const float* __restrict__ am,
                                              const float* __restrict__ lm,
                                              const int* __restrict__ tg){
  int b = blockIdx.z, s0 = blockIdx.y*64, t0 = blockIdx.x*64;
  __shared__ float Ls[64][17], Am[64][17];
  int tid = threadIdx.x;
  int ty = tid>>4, tx = tid&15;
  float acc[4][4];
  #pragma unroll
  for(int i=0;i<4;i++)
    #pragma unroll
    for(int j=0;j<4;j++) acc[i][j]=0.f;

  int lr = tid>>2, lq = (tid&3)*4;
  for(int c0=0;c0<NC;c0+=16){
    {
      int s = s0 + lr;
      float4 v = (s<NS1) ? *(const float4*)&g_lm_p[((size_t)b*NS1+s)*NC + c0 + lq]
                         : make_float4(0.f,0.f,0.f,0.f);
      Ls[lr][lq]=v.x; Ls[lr][lq+1]=v.y; Ls[lr][lq+2]=v.z; Ls[lr][lq+3]=v.w;
    }
    {
      float4 v = *(const float4*)&g_am_p[((size_t)b*NT + t0 + lr)*NC + c0 + lq];
      Am[lr][lq]=v.x; Am[lr][lq+1]=v.y; Am[lr][lq+2]=v.z; Am[lr][lq+3]=v.w;
    }
    __syncthreads();
    #pragma unroll
    for(int c=0;c<16;c++){
      float a0=Ls[ty*4+0][c], a1=Ls[ty*4+1][c], a2=Ls[ty*4+2][c], a3=Ls[ty*4+3][c];
      float e0=Am[tx*4+0][c], e1=Am[tx*4+1][c], e2=Am[tx*4+2][c], e3=Am[tx*4+3][c];
      acc[0][0]+=a0*e0; acc[0][1]+=a0*e1; acc[0][2]+=a0*e2; acc[0][3]+=a0*e3;
      acc[1][0]+=a1*e0; acc[1][1]+=a1*e1; acc[1][2]+=a1*e2; acc[1][3]+=a1*e3;
      acc[2][0]+=a2*e0; acc[2][1]+=a2*e1; acc[2][2]+=a2*e2; acc[2][3]+=a2*e3;
      acc[3][0]+=a3*e0; acc[3][1]+=a3*e1; acc[3][2]+=a3*e2; acc[3][3]+=a3*e3;
    }
    __syncthreads();
  }
  #pragma unroll
  for(int i=0;i<4;i++){
    int s = s0 + ty*4 + i;
    if(s >= NS1) continue;
    float lmx = g_lm_max[b*NS1+s];
    float lse = g_lm_lse[b*NS1+s];
    float lm0 = lm[((size_t)b*NS1+s)*NC];
    int sym = (s<NS) ? tg[b*NS+s] : 0;
    float lms = (s<NS) ? lm[((size_t)b*NS1+s)*NC + sym] : 0.f;
    #pragma unroll
    for(int j=0;j<4;j++){
      int t = t0 + tx*4 + j;
      float nrm = logf(acc[i][j]) + lmx + g_am_max[b*NT+t];
      float am0 = am[((size_t)b*NT+t)*NC];
      g_py[((size_t)b*NS1+s)*NT+t] = 0.75f*(am0+lm0-nrm) + 0.25f*(lm0-lse);
      if(s<NS){
        float ams = am[((size_t)b*NT+t)*NC + sym];
        g_px[((size_t)b*NS+s)*NT1+t] = 0.75f*(ams+lms-nrm) + 0.25f*(lms-lse);
      }
    }
  }
}

// ---------------- W conversion + px t=NT sentinel init ----------------------
__global__ void k_convW(const float* __restrict__ w){
  int idx = blockIdx.x*blockDim.x + threadIdx.x;
  if(idx < NC*NC) g_W[idx] = __float2bfloat16(w[idx]);
  if(idx < NB*NS) g_px[(size_t)idx*NT1 + NT] = NEGF;
}

// ------ lattice DP: coarse wavefront, 65 threads, R=2 rows x W=8 cols -------
// dir 0 (alpha): thread i owns rows 2i,2i+1; chunk c = t in [8c,8c+8); step d: c=d-i.
// dir 1 (beta):  thread i owns rows NS-2i, NS-2i-1; chunks processed descending.
__global__ void __launch_bounds__(65) k_dp(int which){
  int b = blockIdx.x;
  int dir = blockIdx.y;
  const float* PX = (which ? g_pxf : g_px) + (size_t)b*NS*NT1;
  const float* PY = (which ? g_pyf : g_py) + (size_t)b*NS1*NT;
  float* TOT = which ? g_total2 : g_total;
  int i = threadIdx.x;
  __shared__ float prevbuf[2][65][9];   // padded stride 9: conflict-free

  if(dir==0){
    int s0 = 2*i, s1 = 2*i+1;
    bool hasB = (s1 <= NS);
    float* AL = g_alpha + (size_t)b*NS1*NT1P;
    const float* pxa_row = PX + (size_t)(s0>0 ? s0-1 : 0)*NT1;
    const float* pxb_row = PX + (size_t)(hasB ? s0 : 0)*NT1;   // row s1-1 = s0
    const float* pya_row = PY + (size_t)s0*NT;
    const float* pyb_row = PY + (size_t)(hasB ? s1 : 0)*NT;
    float cxa[8],cxb[8],cya[8],cyb[8], nxa[8],nxb[8],nya[8],nyb[8];
    auto LOADF = [&](int c, float* xa, float* xb, float* ya, float* yb){
      c = c<0?0:(c>64?64:c);
      #pragma unroll
      for(int j=0;j<8;j++){
        int t = 8*c+j; int tc = t>512?512:t;
        int tm = t-1; tm = tm<0?0:(tm>511?511:tm);
        xa[j] = __ldg(&pxa_row[tc]);
        xb[j] = __ldg(&pxb_row[tc]);
        ya[j] = __ldg(&pya_row[tm]);
        yb[j] = __ldg(&pyb_row[tm]);
      }
    };
    LOADF(0, cxa,cxb,cya,cyb);
    float pA = NEGF, pB = NEGF;
    float aregs[8], bregs[8];
    for(int d=0; d<=128; ++d){
      int c = d - i;
      LOADF(c+1, nxa,nxb,nya,nyb);
      if(c>=0 && c<=64){
        #pragma unroll
        for(int j=0;j<8;j++){
          int t = 8*c+j;
          if(t<=512){
            float vv = (s0>0) ? prevbuf[d&1][i-1][j] + cxa[j] : NEGF;
            float vh = (t>0) ? pA + cya[j] : NEGF;
            float a = (s0==0 && t==0) ? 0.f : lae2(vv,vh);
            pA = a; aregs[j] = a;
            if(hasB){
              float vv2 = a + cxb[j];
              float vh2 = (t>0) ? pB + cyb[j] : NEGF;
              float bb = lae2(vv2,vh2);
              pB = bb; bregs[j] = bb;
            }
          }
        }
        #pragma unroll
        for(int j=0;j<8;j++) prevbuf[(d+1)&1][i][j] = hasB ? bregs[j] : aregs[j];
        if(!which){
          if(c<64){
            *(float4*)&AL[(size_t)s0*NT1P + 8*c]   = make_float4(aregs[0],aregs[1],aregs[2],aregs[3]);
            *(float4*)&AL[(size_t)s0*NT1P + 8*c+4] = make_float4(aregs[4],aregs[5],aregs[6],aregs[7]);
            if(hasB){
              *(float4*)&AL[(size_t)s1*NT1P + 8*c]   = make_float4(bregs[0],bregs[1],bregs[2],bregs[3]);
              *(float4*)&AL[(size_t)s1*NT1P + 8*c+4] = make_float4(bregs[4],bregs[5],bregs[6],bregs[7]);
            }
          } else {
            AL[(size_t)s0*NT1P + 512] = aregs[0];
            if(hasB) AL[(size_t)s1*NT1P + 512] = bregs[0];
          }
        }
      }
      __syncthreads();
      #pragma unroll
      for(int j=0;j<8;j++){ cxa[j]=nxa[j]; cxb[j]=nxb[j]; cya[j]=nya[j]; cyb[j]=nyb[j]; }
    }
    if(i==64) TOT[b] = pA;
  } else {
    int sA = NS - 2*i, sB = sA - 1;
    bool hasB = (sB >= 0);
    float* BE = g_beta + (size_t)b*NS1*NT1P;
    const float* pxa_row = PX + (size_t)(sA<NS ? sA : 0)*NT1;
    const float* pxb_row = PX + (size_t)(hasB ? sB : 0)*NT1;
    const float* pya_row = PY + (size_t)sA*NT;
    const float* pyb_row = PY + (size_t)(hasB ? sB : 0)*NT;
    float cxa[8],cxb[8],cya[8],cyb[8], nxa[8],nxb[8],nya[8],nyb[8];
    auto LOADB = [&](int c, float* xa, float* xb, float* ya, float* yb){
      c = c<0?0:(c>64?64:c);
      #pragma unroll
      for(int j=0;j<8;j++){
        int t = 8*c+j; int tc = t>512?512:t;
        int ty = t>511?511:t;
        xa[j] = __ldg(&pxa_row[tc]);
        xb[j] = __ldg(&pxb_row[tc]);
        ya[j] = __ldg(&pya_row[ty]);
        yb[j] = __ldg(&pyb_row[ty]);
      }
    };
    LOADB(64, cxa,cxb,cya,cyb);
    float pA = NEGF, pB = NEGF;
    float aregs[8], bregs[8];
    for(int d=0; d<=128; ++d){
      int c = 64 - (d - i);
      LOADB(c-1, nxa,nxb,nya,nyb);
      if(c>=0 && c<=64){
        #pragma unroll
        for(int j=7;j>=0;j--){
          int t = 8*c+j;
          if(t<=512){
            float vv = (sA<NS) ? prevbuf[d&1][i-1][j] + cxa[j] : NEGF;
            float vh = (t<512) ? pA + cya[j] : NEGF;
            float a = (sA==NS && t==512) ? 0.f : lae2(vv,vh);
            pA = a; aregs[j] = a;
            if(hasB){
              float vv2 = a + cxb[j];
              float vh2 = (t<512) ? pB + cyb[j] : NEGF;
              float bb = lae2(vv2,vh2);
              pB = bb; bregs[j] = bb;
            }
          }
        }
        #pragma unroll
        for(int j=0;j<8;j++) prevbuf[(d+1)&1][i][j] = hasB ? bregs[j] : aregs[j];
        if(c<64){
          *(float4*)&BE[(size_t)sA*NT1P + 8*c]   = make_float4(aregs[0],aregs[1],aregs[2],aregs[3]);
          *(float4*)&BE[(size_t)sA*NT1P + 8*c+4] = make_float4(aregs[4],aregs[5],aregs[6],aregs[7]);
          if(hasB){
            *(float4*)&BE[(size_t)sB*NT1P + 8*c]   = make_float4(bregs[0],bregs[1],bregs[2],bregs[3]);
            *(float4*)&BE[(size_t)sB*NT1P + 8*c+4] = make_float4(bregs[4],bregs[5],bregs[6],bregs[7]);
          }
        } else {
          BE[(size_t)sA*NT1P + 512] = aregs[0];
          if(hasB) BE[(size_t)sB*NT1P + 512] = bregs[0];
        }
      }
      __syncthreads();
      #pragma unroll
      for(int j=0;j<8;j++){ cxa[j]=nxa[j]; cxb[j]=nxb[j]; cya[j]=nya[j]; cyb[j]=nyb[j]; }
    }
  }
}

// ---------------- occupancy grads (merged) ----------------
__global__ void k_grads(){
  int idx = blockIdx.x*blockDim.x + threadIdx.x;
  const int N1 = NB*NS*NT1;
  if(idx < N1){
    int t = idx % NT1; int s = (idx/NT1) % NS; int b = idx/(NS*NT1);
    float a  = g_alpha[((size_t)b*NS1+s)*NT1P + t];
    float be = g_beta [((size_t)b*NS1+s+1)*NT1P + t];
    g_pxg[idx] = expf(a + g_px[idx] + be - g_total[b]);
  } else {
    int k = idx - N1;
    if(k >= NB*NS1*NT) return;
    int t = k % NT; int s = (k/NT) % NS1; int b = k/(NS1*NT);
    float a  = g_alpha[((size_t)b*NS1+s)*NT1P + t];
    float be = g_beta [((size_t)b*NS1+s)*NT1P + t + 1];
    g_pyg[k] = expf(a + g_py[k] + be - g_total[b]);
  }
}

// ---------------- pruning window argmax ----------------
__global__ void k_sbegin(){
  int idx = blockIdx.x*blockDim.x + threadIdx.x;
  if(idx >= NB*NT) return;
  int b = idx / NT, t = idx % NT;
  float U[NS1+1];
  U[0] = 0.f;
  for(int s=0;s<=NS;s++){
    float u = g_pyg[((size_t)b*NS1+s)*NT + t];
    if(s < NS) u += g_pxg[((size_t)b*NS+s)*NT1 + t];
    U[s+1] = U[s] + u;
  }
  float best = -3.4e38f; int arg = 0;
  for(int w=0; w<=NS1-RR; w++){
    float v = U[w+RR] - U[w];
    if(v > best){ best = v; arg = w; }
  }
  g_sb[idx] = arg;
}

__global__ void k_adjust(){
  int b = threadIdx.x;
  if(b >= NB) return;
  int m = 1<<30, ym = 1<<30;
  for(int t=NT-1; t>=0; --t){
    int v = g_sb[b*NT+t];
    m = min(m, v);
    int y = (RR-1)*t - m;
    ym = min(ym, y);
    int yc = max(ym, 0);
    g_sb[b*NT+t] = (RR-1)*t - yc;
  }
}

// ---------------- joiner band build (tanh.approx, bf16x2 stores) ------------
__global__ void k_buildA(const float* __restrict__ am, const float* __restrict__ lm){
  int b = blockIdx.x / NT, t = blockIdx.x % NT;
  __shared__ float amr[NC];
  for(int c=threadIdx.x;c<NC;c+=256) amr[c]=am[((size_t)b*NT+t)*NC+c];
  __syncthreads();
  int sb = g_sb[b*NT+t];
  size_t base = (size_t)(b*NT+t)*RR;
  int c = threadIdx.x*2;
  for(int j=0;j<RR;j++){
    const float* lr = lm + ((size_t)(b*NS1 + sb + j))*NC;
    float2 lv = *(const float2*)&lr[c];
    __nv_bfloat162 o;
    o.x = __float2bfloat16(tanh_ap(amr[c]   + lv.x));
    o.y = __float2bfloat16(tanh_ap(amr[c+1] + lv.y));
    *(__nv_bfloat162*)&g_A[(base+j)*NC + c] = o;
  }
}

// ---- joiner GEMM + fused band epilogue -------------------------------------
#define AP 40
#define BP 136
#define AST (128*AP)
#define BST (32*BP)
__global__ void __launch_bounds__(256) k_gemm(const int* __restrict__ tg,
                                              const float* __restrict__ bias){
  __shared__ __align__(16) char sbuf[(2*AST + 2*BST)*2];
  __nv_bfloat16* As = (__nv_bfloat16*)sbuf;
  __nv_bfloat16* Bs = (__nv_bfloat16*)(sbuf + 2*AST*2);
  int bn = blockIdx.x*128, bm = blockIdx.y*128;
  int tid = threadIdx.x, warp = tid>>5, lane = tid&31;
  int wm = warp & 1, wn = warp >> 1;
  uint32_t asb = (uint32_t)__cvta_generic_to_shared(As);
  uint32_t bsb = (uint32_t)__cvta_generic_to_shared(Bs);

  wmma::fragment<wmma::accumulator,16,16,16,float> acc[4][2];
  #pragma unroll
  for(int i=0;i<4;i++)
    #pragma unroll
    for(int j=0;j<2;j++) wmma::fill_fragment(acc[i][j], 0.f);

  auto loadst = [&](int ki, int st){
    #pragma unroll
    for(int it=0;it<2;it++){
      int v = tid + it*256, row = v>>2, q = v&3;
      cp16(asb + (st*AST + row*AP)*2 + q*16,
           &g_A[(size_t)(bm+row)*NC + ki*32 + q*8]);
    }
    #pragma unroll
    for(int it=0;it<2;it++){
      int v = tid + it*256, row = v>>4, q = v&15;
      cp16(bsb + (st*BST + row*BP)*2 + q*16,
           &g_W[(size_t)(ki*32+row)*NC + bn + q*8]);
    }
    asm volatile("cp.async.commit_group;");
  };

  loadst(0,0);
  for(int k=0;k<16;k++){
    int cur = k&1;
    if(k<15){
      loadst(k+1, cur^1);
      asm volatile("cp.async.wait_group 1;");
    } else {
      asm volatile("cp.async.wait_group 0;");
    }
    __syncthreads();
    __nv_bfloat16* Ac = As + cur*AST;
    __nv_bfloat16* Bc = Bs + cur*BST;
    #pragma unroll
    for(int kk=0;kk<2;kk++){
      wmma::fragment<wmma::matrix_a,16,16,16,__nv_bfloat16,wmma::row_major> a[4];
      wmma::fragment<wmma::matrix_b,16,16,16,__nv_bfloat16,wmma::row_major> bfr[2];
      #pragma unroll
      for(int i=0;i<4;i++) wmma::load_matrix_sync(a[i], &Ac[(wm*64+i*16)*AP + kk*16], AP);
      #pragma unroll
      for(int j=0;j<2;j++) wmma::load_matrix_sync(bfr[j], &Bc[(kk*16)*BP + wn*32 + j*16], BP);
      #pragma unroll
      for(int i=0;i<4;i++)
        #pragma unroll
        for(int j=0;j<2;j++) wmma::mma_sync(acc[i][j], a[i], bfr[j], acc[i][j]);
    }
    __syncthreads();
  }

  float* Sg = (float*)sbuf;
  #pragma unroll
  for(int ph=0; ph<2; ph++){
    if(wm == ph){
      #pragma unroll
      for(int i=0;i<4;i++)
        #pragma unroll
        for(int j=0;j<2;j++)
          wmma::store_matrix_sync(&Sg[(i*16)*132 + wn*32 + j*16], acc[i][j], 132,
                                  wmma::mem_row_major);
    }
    __syncthreads();
    #pragma unroll
    for(int q=0;q<8;q++){
      int r = warp*8 + q;
      float4 v4 = *(float4*)&Sg[r*132 + lane*4];
      float4 b4 = *(const float4*)&bias[bn + lane*4];
      float x0=v4.x+b4.x, x1=v4.y+b4.y, x2=v4.z+b4.z, x3=v4.w+b4.w;
      float mx = warpmax(fmaxf(fmaxf(x0,x1),fmaxf(x2,x3)));
      float ss = warpsum(expf(x0-mx)+expf(x1-mx)+expf(x2-mx)+expf(x3-mx));
      if(lane==0){
        int gr = bm + ph*64 + r;
        g_pmax[(size_t)gr*4 + blockIdx.x] = mx;
        g_psum[(size_t)gr*4 + blockIdx.x] = ss;
        int j = gr % RR; int bt = gr/RR; int b = bt/NT;
        int rng = g_sb[bt] + j;
        int sym = (rng < NS) ? tg[b*NS + rng] : 0;
        int sc = sym - bn;
        if(sc >= 0 && sc < 128) g_pxv[gr] = Sg[r*132 + sc] + bias[sym];
        if(bn == 0)             g_pyv[gr] = Sg[r*132]      + bias[0];
      }
    }
    __syncthreads();
  }
}

// ------- scatter band to full lattice, combining N-partial lse inline -------
__device__ __forceinline__ float band_lse(int gr){
  float4 m4 = *(const float4*)&g_pmax[(size_t)gr*4];
  float4 s4 = *(const float4*)&g_psum[(size_t)gr*4];
  float M = fmaxf(fmaxf(m4.x,m4.y), fmaxf(m4.z,m4.w));
  float S = s4.x*expf(m4.x-M) + s4.y*expf(m4.y-M) + s4.z*expf(m4.z-M) + s4.w*expf(m4.w-M);
  return M + logf(S);
}
__global__ void k_scatter(){
  int idx = blockIdx.x*blockDim.x + threadIdx.x;
  const int N1 = NB*NS*NT1;
  if(idx < N1){
    int t = idx % NT1; int s = (idx/NT1) % NS; int b = idx/(NS*NT1);
    float v = NEGF;
    if(t < NT){
      int sb = g_sb[b*NT+t]; int j = s - sb;
      if(j>=0 && j<RR){
        int gr = (b*NT+t)*RR + j;
        v = g_pxv[gr] - band_lse(gr);
      }
    }
    g_pxf[idx] = v;
  } else {
    int k = idx - N1;
    if(k >= NB*NS1*NT) return;
    int t = k % NT; int s = (k/NT) % NS1; int b = k/(NS1*NT);
    int sb = g_sb[b*NT+t]; int j = s - sb;
    float v = NEGF;
    if(j>=0 && j<RR){
      int gr = (b*NT+t)*RR + j;
      v = g_pyv[gr] - band_lse(gr);
    }
    g_pyf[k] = v;
  }
}

// ---------------- final loss ----------------
__global__ void k_final(float* out){
  float a=0.f, c=0.f;
  for(int b=0;b<NB;b++){ a += g_total[b]; c += g_total2[b]; }
  out[0] = -(0.1f*a + c)/(float)NB;
}

extern "C" void kernel_launch(void* const* d_in, const int* in_sizes, int n_in,
                              void* d_out, int out_size) {
  const float* am  = (const float*)d_in[0];
  const float* lm  = (const float*)d_in[1];
  const int*   tg  = (const int*)  d_in[2];
  const float* jw  = (const float*)d_in[4];
  const float* jb  = (const float*)d_in[5];
  float* out = (float*)d_out;
  (void)in_sizes; (void)n_in; (void)out_size;

  const int NPXY = NB*NS*NT1 + NB*NS1*NT;

  k_stats<<<(NB*NS1 + NB*NT + 7)/8, 256>>>(lm, am);     // 0
  k_norm<<<dim3(NT/64, 3, NB), 256>>>(am, lm, tg);      // 1
  k_convW<<<(NC*NC+255)/256, 256>>>(jw);                // 2
  k_dp<<<dim3(NB,2), 65>>>(0);                          // 3  <- profiled slot
  k_grads<<<(NPXY+255)/256, 256>>>();                   // 4
  k_sbegin<<<(NB*NT+255)/256, 256>>>();                 // 5
  k_adjust<<<1, NB>>>();                                // 6
  k_buildA<<<NB*NT, 256>>>(am, lm);                     // 7
  k_gemm<<<dim3(4, MROWS/128), 256>>>(tg, jb);          // 8
  k_scatter<<<(NPXY+255)/256, 256>>>();                 // 9
  k_dp<<<dim3(NB,1), 65>>>(1);                          // 10
  k_final<<<1,1>>>(out);                                // 11
}